// round 15
// baseline (speedup 1.0000x reference)
#include <cuda_runtime.h>
#include <cstdint>

// EMA along last axis: acc_t = w*x_t + (1-w)*acc_{t-1}
// [B,C,F,T] fp32, T=6000 contiguous; 4112 independent sequences.
//
// One WARP per sequence, 128-element segments (lane k owns times 4k..4k+3:
// every LDG.128/STG.128 is a dense 512B transaction). Cross-lane coupling
// via shuffle affine scan (coeff a^4), computed EXCLUSIVE directly (pre-
// shift by 1 lane, then 5-step inclusive scan; lane-31 total recovered
// with one FMA) -> 6 shuffles/segment instead of 7. Carry chains in a
// register. Zero smem/barriers. 4-segment-deep load prefetch.
//
// L2 policy (steady-state replay loop):
//   loads : fractional evict_last 0.8 / evict_first secondary
//           (~79MB of input pinned with headroom; rest streams)
//   stores: evict_first (writes stream through L2 to DRAM)

constexpr int T_LEN     = 6000;
constexpr int SEG       = 128;                // 32 lanes x 4 floats
constexpr int NFULL     = T_LEN / SEG;        // 46
constexpr int REM       = T_LEN - NFULL*SEG;  // 112
constexpr int REM_LANES = REM / 4;            // 28
constexpr int WPB       = 4;                  // warps per block

__device__ __forceinline__ float4 ldg_hint(const float4* p, uint64_t pol) {
    float4 v;
    asm("ld.global.L2::cache_hint.v4.f32 {%0,%1,%2,%3}, [%4], %5;"
        : "=f"(v.x), "=f"(v.y), "=f"(v.z), "=f"(v.w) : "l"(p), "l"(pol));
    return v;
}
__device__ __forceinline__ void stg_hint(float4* p, float4 v, uint64_t pol) {
    asm volatile("st.global.L2::cache_hint.v4.f32 [%0], {%1,%2,%3,%4}, %5;"
                 :: "l"(p), "f"(v.x), "f"(v.y), "f"(v.z), "f"(v.w), "l"(pol)
                 : "memory");
}

__global__ __launch_bounds__(WPB * 32)
void ema_kernel(const float* __restrict__ x,
                const float* __restrict__ init,
                const float* __restrict__ wptr,
                float* __restrict__ out,
                int nseq)
{
    const int lane = threadIdx.x & 31;
    const int wid  = threadIdx.x >> 5;
    const int seq  = blockIdx.x * WPB + wid;
    if (seq >= nseq) return;                  // warp-uniform exit

    uint64_t pol_in, pol_out;
    asm("createpolicy.fractional.L2::evict_last.L2::evict_first.b64 %0, 0.8;"
        : "=l"(pol_in));
    asm("createpolicy.fractional.L2::evict_first.b64 %0, 1.0;" : "=l"(pol_out));

    const float w  = fminf(fmaxf(wptr[0], 0.0f), 1.0f);
    const float a  = 1.0f - w;
    const float a2 = a * a;
    const float a3 = a2 * a;
    const float a4 = a2 * a2;
    const float alane = powf(a4, (float)lane);  // a^(4*lane)
    const float a128  = powf(a4, 32.0f);        // a^128

    const float4* xp = reinterpret_cast<const float4*>(x + (size_t)seq * T_LEN);
    float4*       op = reinterpret_cast<float4*>(out + (size_t)seq * T_LEN);

    float carry = init[seq];                  // state entering current segment

    // predicated dense segment load (seg j; j==NFULL is the 112-elem tail)
    auto load_seg = [&](int j) -> float4 {
        if (j < NFULL)                      return ldg_hint(xp + j * 32 + lane, pol_in);
        if (j == NFULL && lane < REM_LANES) return ldg_hint(xp + j * 32 + lane, pol_in);
        return make_float4(0.f, 0.f, 0.f, 0.f);
    };

    auto process = [&](float4 c, int segi, bool store_ok) {
        float local0 = w * c.x;
        float local1 = fmaf(w, c.y, a * local0);
        float local2 = fmaf(w, c.z, a * local1);
        float local3 = fmaf(w, c.w, a * local2);
        const float e = local3;                   // this lane's chunk sum

        // EXCLUSIVE affine scan over lanes, computed directly:
        // shift e by one lane, then 5-step inclusive scan with coeff a4.
        float Dex = __shfl_up_sync(0xffffffffu, e, 1);
        Dex = (lane == 0) ? 0.0f : Dex;
        float sc = a4;
        #pragma unroll
        for (int s = 1; s < 32; s <<= 1) {
            float p = __shfl_up_sync(0xffffffffu, Dex, s);
            if (lane >= s) Dex = fmaf(sc, p, Dex);
            sc *= sc;
        }
        // Dex(lane) = sum_{j<lane} a4^(lane-1-j) e_j  (exclusive total)

        float C = fmaf(alane, carry, Dex);        // incoming state, this lane

        // inclusive total at lane 31 = a4*Dex_31 + e_31 (one fma, one bcast)
        float Dex31 = __shfl_sync(0xffffffffu, Dex, 31);
        float e31   = __shfl_sync(0xffffffffu, e, 31);
        carry = fmaf(a128, carry, fmaf(a4, Dex31, e31));

        if (store_ok) {
            float4 y = make_float4(fmaf(a,  C, local0),
                                   fmaf(a2, C, local1),
                                   fmaf(a3, C, local2),
                                   fmaf(a4, C, local3));
            stg_hint(op + segi * 32 + lane, y, pol_out);
        }
    };

    // 4-deep prefetch: b0..b3 hold segments i..i+3
    float4 b0 = load_seg(0);
    float4 b1 = load_seg(1);
    float4 b2 = load_seg(2);
    float4 b3 = load_seg(3);

    #pragma unroll 1
    for (int i = 0; i < NFULL; i += 2) {       // 23 iterations
        float4 c0 = b0, c1 = b1;
        b0 = b2; b1 = b3;
        // issue next loads BEFORE the serial scan chain
        b2 = load_seg(i + 4);
        b3 = load_seg(i + 5);
        process(c0, i,     true);
        process(c1, i + 1, true);
    }

    // tail segment 46 (112 elems) is sitting in b0 after the final shift
    process(b0, NFULL, lane < REM_LANES);
}

extern "C" void kernel_launch(void* const* d_in, const int* in_sizes, int n_in,
                              void* d_out, int out_size)
{
    const float* x    = (const float*)d_in[0];   // mag_spec  [B,C,F,T]
    const float* init = (const float*)d_in[1];   // initial_state [B,C,F,1]
    const float* wp   = (const float*)d_in[2];   // weights [1]
    float*       out  = (float*)d_out;

    const int nseq = in_sizes[1];                // B*C*F = 4112
    const int blocks = (nseq + WPB - 1) / WPB;   // 1028
    ema_kernel<<<blocks, WPB * 32>>>(x, init, wp, out, nseq);
}